// round 7
// baseline (speedup 1.0000x reference)
#include <cuda_runtime.h>
#include <cuda_bf16.h>
#include <cstdint>

#define MAX_N 100000

// Split-plane intermediates and weights (hi/lo bf16 planes)
__device__ __align__(16) __nv_bfloat16 g_mid1h[MAX_N * 64];
__device__ __align__(16) __nv_bfloat16 g_mid1l[MAX_N * 64];
__device__ __align__(16) __nv_bfloat16 g_mid2h[MAX_N * 64];
__device__ __align__(16) __nv_bfloat16 g_mid2l[MAX_N * 64];
__device__ __align__(16) __nv_bfloat16 g_w1h[64 * 256], g_w1l[64 * 256];
__device__ __align__(16) __nv_bfloat16 g_w2h[9 * 64 * 64], g_w2l[9 * 64 * 64];
__device__ __align__(16) __nv_bfloat16 g_w3h[256 * 64], g_w3l[256 * 64];

// ---------------- helpers ----------------
__device__ __forceinline__ uint32_t smem_u32(const void* p) {
    uint32_t a;
    asm("{ .reg .u64 t; cvta.to.shared.u64 t, %1; cvt.u32.u64 %0, t; }" : "=r"(a) : "l"(p));
    return a;
}
__device__ __forceinline__ void split2(float a, float b, uint32_t& h, uint32_t& l) {
    __nv_bfloat16 ha = __float2bfloat16(a), hb = __float2bfloat16(b);
    __nv_bfloat16 la = __float2bfloat16(a - __bfloat162float(ha));
    __nv_bfloat16 lb = __float2bfloat16(b - __bfloat162float(hb));
    h = (uint32_t)__bfloat16_as_ushort(ha) | ((uint32_t)__bfloat16_as_ushort(hb) << 16);
    l = (uint32_t)__bfloat16_as_ushort(la) | ((uint32_t)__bfloat16_as_ushort(lb) << 16);
}
__device__ __forceinline__ void cpa16(uint32_t dst, const void* src, int srcsize) {
    asm volatile("cp.async.cg.shared.global [%0], [%1], 16, %2;"
                 :: "r"(dst), "l"(src), "r"(srcsize));
}
__device__ __forceinline__ void cpa16u(uint32_t dst, const void* src) {
    asm volatile("cp.async.cg.shared.global [%0], [%1], 16;"
                 :: "r"(dst), "l"(src));
}
#define CP_COMMIT() asm volatile("cp.async.commit_group;" ::: "memory")
#define CP_WAIT1()  asm volatile("cp.async.wait_group 1;" ::: "memory")
#define CP_WAIT0()  asm volatile("cp.async.wait_group 0;" ::: "memory")

__device__ __forceinline__ void mma_bf16(float* c, const uint32_t* a, uint32_t b0, uint32_t b1) {
    asm volatile(
        "mma.sync.aligned.m16n8k16.row.col.f32.bf16.bf16.f32 "
        "{%0,%1,%2,%3}, {%4,%5,%6,%7}, {%8,%9}, {%0,%1,%2,%3};"
        : "+f"(c[0]), "+f"(c[1]), "+f"(c[2]), "+f"(c[3])
        : "r"(a[0]), "r"(a[1]), "r"(a[2]), "r"(a[3]), "r"(b0), "r"(b1));
}
__device__ __forceinline__ void ldsm4(uint32_t* r, uint32_t a) {
    asm volatile("ldmatrix.sync.aligned.m8n8.x4.shared.b16 {%0,%1,%2,%3}, [%4];"
                 : "=r"(r[0]), "=r"(r[1]), "=r"(r[2]), "=r"(r[3]) : "r"(a));
}

struct AF { uint32_t h[4], l[4]; };
struct BF2 { uint32_t h[4], l[4]; };

__device__ __forceinline__ AF load_af(uint32_t hU, uint32_t lU, int lane, int m0, int kc0) {
    int row = m0 + (lane & 15);
    int kc = kc0 + (lane >> 4);
    uint32_t off = row * 128 + (((kc ^ row) & 7)) * 16;
    AF f; ldsm4(f.h, hU + off); ldsm4(f.l, lU + off);
    return f;
}
__device__ __forceinline__ BF2 load_bf2(uint32_t hU, uint32_t lU, int stride, int lane,
                                        int n0, int kc0) {
    int row = n0 + (lane & 7) + ((lane >> 4) << 3);
    int kc = kc0 + ((lane >> 3) & 1);
    uint32_t off = row * stride + ((kc & ~7) | ((kc ^ row) & 7)) * 16;
    BF2 f; ldsm4(f.h, hU + off); ldsm4(f.l, lU + off);
    return f;
}
__device__ __forceinline__ void mma3v(float* c, const AF& a, uint32_t bh0, uint32_t bh1,
                                      uint32_t bl0, uint32_t bl1) {
    mma_bf16(c, a.h, bh0, bh1);
    mma_bf16(c, a.h, bl0, bl1);
    mma_bf16(c, a.l, bh0, bh1);
}

// ---------------- prep ----------------
__global__ void prep_weights(const float* __restrict__ w1, const float* __restrict__ w2,
                             const float* __restrict__ w3) {
    int tid = blockIdx.x * blockDim.x + threadIdx.x;
    int nt = gridDim.x * blockDim.x;
    for (int i = tid; i < 64 * 256; i += nt) {
        int n = i >> 8, k = i & 255;
        float x = w1[k * 64 + n];
        __nv_bfloat16 h = __float2bfloat16(x);
        g_w1h[i] = h; g_w1l[i] = __float2bfloat16(x - __bfloat162float(h));
    }
    for (int i = tid; i < 9 * 64 * 64; i += nt) {
        int ko = i >> 12, n = (i >> 6) & 63, k = i & 63;
        float x = w2[ko * 4096 + k * 64 + n];
        __nv_bfloat16 h = __float2bfloat16(x);
        g_w2h[i] = h; g_w2l[i] = __float2bfloat16(x - __bfloat162float(h));
    }
    for (int i = tid; i < 256 * 64; i += nt) {
        int n = i >> 6, k = i & 63;
        float x = w3[k * 256 + n];
        __nv_bfloat16 h = __float2bfloat16(x);
        g_w3h[i] = h; g_w3l[i] = __float2bfloat16(x - __bfloat162float(h));
    }
}

// ===========================================================================
// conv1: M64 tiles, K=256 (4 panels), 256 thr, 2 CTAs/SM. Clamped batched loads.
// ===========================================================================
__global__ void __launch_bounds__(256, 2) conv1_k(
    const float* __restrict__ feat, const float* __restrict__ scale,
    const float* __restrict__ bias, int N, int tiles)
{
    extern __shared__ char smem[];
    const uint32_t smU = smem_u32(smem);
    const int tid = threadIdx.x, w = tid >> 5, lane = tid & 31;
    const int g = lane >> 2, tg = lane & 3;
    const int m0w = (w & 1) * 32, n0w = (w >> 1) * 16;
    const int sr = tid >> 2, sq = tid & 3;

    for (int e = tid; e < 2048; e += 256) {
        int n = e >> 5, kc = e & 31;
        int off = n * 512 + ((kc & ~7) | ((kc ^ n) & 7)) * 16;
        *(uint4*)(smem + off)         = *(const uint4*)(g_w1h + n * 256 + kc * 8);
        *(uint4*)(smem + 32768 + off) = *(const uint4*)(g_w1l + n * 256 + kc * 8);
    }

    float4 nx[4];
    {
        int gc = min((blockIdx.x << 6) + sr, N - 1);
        const float4* s = (const float4*)(feat + (size_t)gc * 256 + sq * 16);
        nx[0] = s[0]; nx[1] = s[1]; nx[2] = s[2]; nx[3] = s[3];
    }
    __syncthreads();

    for (int t = blockIdx.x; t < tiles; t += gridDim.x) {
        const int row0 = t << 6;
        float C[2][2][4] = {};
        #pragma unroll
        for (int p = 0; p < 4; p++) {
            char* Ah = smem + 65536 + (p & 1) * 16384;
            char* Al = Ah + 8192;
            #pragma unroll
            for (int j = 0; j < 2; j++) {
                float4 u = nx[2 * j], v = nx[2 * j + 1];
                uint4 H, L;
                split2(u.x, u.y, H.x, L.x); split2(u.z, u.w, H.y, L.y);
                split2(v.x, v.y, H.z, L.z); split2(v.z, v.w, H.w, L.w);
                int c = sq * 2 + j;
                int off = sr * 128 + ((c ^ sr) & 7) * 16;
                *(uint4*)(Ah + off) = H; *(uint4*)(Al + off) = L;
            }
            __syncthreads();
            {
                int tn = (p < 3) ? t : t + gridDim.x;
                int pn = (p < 3) ? p + 1 : 0;
                int gc = min((tn << 6) + sr, N - 1);
                const float4* s = (const float4*)(feat + (size_t)gc * 256 + pn * 64 + sq * 16);
                nx[0] = s[0]; nx[1] = s[1]; nx[2] = s[2]; nx[3] = s[3];
            }
            const uint32_t AhU = smU + 65536 + (p & 1) * 16384, AlU = AhU + 8192;
            #pragma unroll
            for (int s = 0; s < 4; s++) {
                AF a0 = load_af(AhU, AlU, lane, m0w, s * 2);
                AF a1 = load_af(AhU, AlU, lane, m0w + 16, s * 2);
                BF2 b = load_bf2(smU, smU + 32768, 512, lane, n0w, p * 8 + s * 2);
                mma3v(C[0][0], a0, b.h[0], b.h[1], b.l[0], b.l[1]);
                mma3v(C[0][1], a0, b.h[2], b.h[3], b.l[2], b.l[3]);
                mma3v(C[1][0], a1, b.h[0], b.h[1], b.l[0], b.l[1]);
                mma3v(C[1][1], a1, b.h[2], b.h[3], b.l[2], b.l[3]);
            }
        }
        #pragma unroll
        for (int mf = 0; mf < 2; mf++)
        #pragma unroll
        for (int nf = 0; nf < 2; nf++) {
            int row = row0 + m0w + mf * 16 + g;
            int col = n0w + nf * 8 + 2 * tg;
            float s0 = __ldg(scale + col), s1 = __ldg(scale + col + 1);
            float bb0 = __ldg(bias + col), bb1 = __ldg(bias + col + 1);
            if (row < N) {
                uint32_t h, l;
                split2(fmaxf(fmaf(C[mf][nf][0], s0, bb0), 0.f),
                       fmaxf(fmaf(C[mf][nf][1], s1, bb1), 0.f), h, l);
                *(uint32_t*)(g_mid1h + (size_t)row * 64 + col) = h;
                *(uint32_t*)(g_mid1l + (size_t)row * 64 + col) = l;
            }
            if (row + 8 < N) {
                uint32_t h, l;
                split2(fmaxf(fmaf(C[mf][nf][2], s0, bb0), 0.f),
                       fmaxf(fmaf(C[mf][nf][3], s1, bb1), 0.f), h, l);
                *(uint32_t*)(g_mid1h + (size_t)(row + 8) * 64 + col) = h;
                *(uint32_t*)(g_mid1l + (size_t)(row + 8) * 64 + col) = l;
            }
        }
    }
}

// ===========================================================================
// conv2: unchanged structure (zero-fill gather mandatory), one sync per ko.
// ===========================================================================
__global__ void __launch_bounds__(512) conv2_k(
    const int* __restrict__ nbr, const float* __restrict__ scale,
    const float* __restrict__ bias, int N, int tiles)
{
    extern __shared__ char smem[];
    const uint32_t smU = smem_u32(smem);
    const uint32_t AU = smU + 147456;
    const int tid = threadIdx.x, w = tid >> 5, lane = tid & 31;
    const int g = lane >> 2, tg = lane & 3;
    const int m0w = (w & 3) * 32, n0w = (w >> 2) * 16;
    const int sr = tid >> 2, sq = tid & 3;

    for (int e = tid; e < 4608; e += 512) {
        int ko = e >> 9, r = e & 511, n = r >> 3, kc = r & 7;
        int off = n * 128 + ((kc ^ n) & 7) * 16;
        *(uint4*)(smem + ko * 16384 + off)        = *(const uint4*)(g_w2h + ko * 4096 + n * 64 + kc * 8);
        *(uint4*)(smem + ko * 16384 + 8192 + off) = *(const uint4*)(g_w2l + ko * 4096 + n * 64 + kc * 8);
    }
    __syncthreads();

    const int c0 = sq * 2, c1 = sq * 2 + 1;
    const uint32_t offA0 = sr * 128 + ((c0 ^ sr) & 7) * 16;
    const uint32_t offA1 = sr * 128 + ((c1 ^ sr) & 7) * 16;

    for (int t = blockIdx.x; t < tiles; t += gridDim.x) {
        const int row0 = t << 7;
        const int grow = row0 + sr;
        int nidx9[9];
        #pragma unroll
        for (int ko = 0; ko < 9; ko++)
            nidx9[ko] = (grow < N) ? __ldg(nbr + (size_t)grow * 9 + ko) : N;

        {
            int nn = nidx9[0];
            int sz = (nn < N) ? 16 : 0;
            size_t base = (size_t)(nn < N ? nn : 0) * 64;
            cpa16(AU + offA0, g_mid1h + base + c0 * 8, sz);
            cpa16(AU + offA1, g_mid1h + base + c1 * 8, sz);
            cpa16(AU + 16384 + offA0, g_mid1l + base + c0 * 8, sz);
            cpa16(AU + 16384 + offA1, g_mid1l + base + c1 * 8, sz);
            CP_COMMIT();
        }

        float C[2][2][4] = {};
        #pragma unroll
        for (int ko = 0; ko < 9; ko++) {
            CP_WAIT0();
            __syncthreads();
            if (ko < 8) {
                int nn = nidx9[ko + 1];
                int sz = (nn < N) ? 16 : 0;
                size_t base = (size_t)(nn < N ? nn : 0) * 64;
                uint32_t Ab = AU + ((ko + 1) & 1) * 32768;
                cpa16(Ab + offA0, g_mid1h + base + c0 * 8, sz);
                cpa16(Ab + offA1, g_mid1h + base + c1 * 8, sz);
                cpa16(Ab + 16384 + offA0, g_mid1l + base + c0 * 8, sz);
                cpa16(Ab + 16384 + offA1, g_mid1l + base + c1 * 8, sz);
                CP_COMMIT();
            }
            const uint32_t AhU = AU + (ko & 1) * 32768, AlU = AhU + 16384;
            const uint32_t BhU = smU + ko * 16384, BlU = BhU + 8192;
            #pragma unroll
            for (int s = 0; s < 4; s++) {
                AF a0 = load_af(AhU, AlU, lane, m0w, s * 2);
                AF a1 = load_af(AhU, AlU, lane, m0w + 16, s * 2);
                BF2 b = load_bf2(BhU, BlU, 128, lane, n0w, s * 2);
                mma3v(C[0][0], a0, b.h[0], b.h[1], b.l[0], b.l[1]);
                mma3v(C[0][1], a0, b.h[2], b.h[3], b.l[2], b.l[3]);
                mma3v(C[1][0], a1, b.h[0], b.h[1], b.l[0], b.l[1]);
                mma3v(C[1][1], a1, b.h[2], b.h[3], b.l[2], b.l[3]);
            }
        }
        #pragma unroll
        for (int mf = 0; mf < 2; mf++)
        #pragma unroll
        for (int nf = 0; nf < 2; nf++) {
            int row = row0 + m0w + mf * 16 + g;
            int col = n0w + nf * 8 + 2 * tg;
            float s0 = __ldg(scale + col), s1 = __ldg(scale + col + 1);
            float bb0 = __ldg(bias + col), bb1 = __ldg(bias + col + 1);
            if (row < N) {
                uint32_t h, l;
                split2(fmaxf(fmaf(C[mf][nf][0], s0, bb0), 0.f),
                       fmaxf(fmaf(C[mf][nf][1], s1, bb1), 0.f), h, l);
                *(uint32_t*)(g_mid2h + (size_t)row * 64 + col) = h;
                *(uint32_t*)(g_mid2l + (size_t)row * 64 + col) = l;
            }
            if (row + 8 < N) {
                uint32_t h, l;
                split2(fmaxf(fmaf(C[mf][nf][2], s0, bb0), 0.f),
                       fmaxf(fmaf(C[mf][nf][3], s1, bb1), 0.f), h, l);
                *(uint32_t*)(g_mid2h + (size_t)(row + 8) * 64 + col) = h;
                *(uint32_t*)(g_mid2l + (size_t)(row + 8) * 64 + col) = l;
            }
        }
        __syncthreads();
    }
}

// ===========================================================================
// conv3: M128 K64, two N128 halves, 256 thr, 2 CTAs/SM.
// Clamped A prefetch; batched clamped feat loads in epilogue.
// ===========================================================================
__global__ void __launch_bounds__(256, 2) conv3_k(
    const float* __restrict__ feat, const float* __restrict__ scale,
    const float* __restrict__ bias, float* __restrict__ out, int N, int tiles)
{
    extern __shared__ char smem[];
    const uint32_t smU = smem_u32(smem);
    const uint32_t AU = smU + 32768;
    const int tid = threadIdx.x, w = tid >> 5, lane = tid & 31;
    const int g = lane >> 2, tg = lane & 3;
    const int nhalf = blockIdx.x & 1;
    const int t0 = blockIdx.x >> 1, tstep = gridDim.x >> 1;
    const int m0w = (w & 3) * 32, n0l = (w >> 2) * 64;
    const int colbase = nhalf * 128;
    const int sr = tid >> 1, sq = tid & 1;

    for (int e = tid; e < 1024; e += 256) {
        int n = e >> 3, kc = e & 7;
        int off = n * 128 + ((kc ^ n) & 7) * 16;
        *(uint4*)(smem + off)         = *(const uint4*)(g_w3h + (colbase + n) * 64 + kc * 8);
        *(uint4*)(smem + 16384 + off) = *(const uint4*)(g_w3l + (colbase + n) * 64 + kc * 8);
    }

    {   // prologue: prefetch tile t0 -> buf0 (clamped rows, unconditional copies)
        int gc = min((t0 << 7) + sr, N - 1);
        size_t base = (size_t)gc * 64;
        #pragma unroll
        for (int j = 0; j < 4; j++) {
            int c = sq * 4 + j;
            uint32_t off = sr * 128 + ((c ^ sr) & 7) * 16;
            cpa16u(AU + off, g_mid2h + base + c * 8);
            cpa16u(AU + 16384 + off, g_mid2l + base + c * 8);
        }
        CP_COMMIT();
    }

    int cnt = 0;
    for (int t = t0; t < tiles; t += tstep) {
        const int row0 = t << 7;
        const int b = cnt & 1;
        {
            int gc = min(((t + tstep) << 7) + sr, N - 1);
            size_t base = (size_t)gc * 64;
            uint32_t Ab = AU + (b ^ 1) * 32768;
            #pragma unroll
            for (int j = 0; j < 4; j++) {
                int c = sq * 4 + j;
                uint32_t off = sr * 128 + ((c ^ sr) & 7) * 16;
                cpa16u(Ab + off, g_mid2h + base + c * 8);
                cpa16u(Ab + 16384 + off, g_mid2l + base + c * 8);
            }
            CP_COMMIT();
        }
        CP_WAIT1();
        __syncthreads();

        const uint32_t AhU = AU + b * 32768, AlU = AhU + 16384;
        float C[2][8][4] = {};
        #pragma unroll
        for (int s = 0; s < 4; s++) {
            AF a0 = load_af(AhU, AlU, lane, m0w, s * 2);
            AF a1 = load_af(AhU, AlU, lane, m0w + 16, s * 2);
            #pragma unroll
            for (int nb = 0; nb < 4; nb++) {
                BF2 bb = load_bf2(smU, smU + 16384, 128, lane, n0l + nb * 16, s * 2);
                mma3v(C[0][2 * nb],     a0, bb.h[0], bb.h[1], bb.l[0], bb.l[1]);
                mma3v(C[0][2 * nb + 1], a0, bb.h[2], bb.h[3], bb.l[2], bb.l[3]);
                mma3v(C[1][2 * nb],     a1, bb.h[0], bb.h[1], bb.l[0], bb.l[1]);
                mma3v(C[1][2 * nb + 1], a1, bb.h[2], bb.h[3], bb.l[2], bb.l[3]);
            }
        }
        #pragma unroll
        for (int mf = 0; mf < 2; mf++) {
            int rowA = row0 + m0w + mf * 16 + g;
            int rowB = rowA + 8;
            size_t rA = (size_t)min(rowA, N - 1) * 256;
            size_t rB = (size_t)min(rowB, N - 1) * 256;
            float2 fA[8], fB[8];
            #pragma unroll
            for (int nf = 0; nf < 8; nf++) {
                int col = colbase + n0l + nf * 8 + 2 * tg;
                fA[nf] = *(const float2*)(feat + rA + col);
                fB[nf] = *(const float2*)(feat + rB + col);
            }
            #pragma unroll
            for (int nf = 0; nf < 8; nf++) {
                int col = colbase + n0l + nf * 8 + 2 * tg;
                float s0 = __ldg(scale + col), s1 = __ldg(scale + col + 1);
                float bb0 = __ldg(bias + col), bb1 = __ldg(bias + col + 1);
                if (rowA < N) {
                    float2 o;
                    o.x = fmaxf(fmaf(C[mf][nf][0], s0, bb0) + fA[nf].x, 0.f);
                    o.y = fmaxf(fmaf(C[mf][nf][1], s1, bb1) + fA[nf].y, 0.f);
                    *(float2*)(out + (size_t)rowA * 256 + col) = o;
                }
                if (rowB < N) {
                    float2 o;
                    o.x = fmaxf(fmaf(C[mf][nf][2], s0, bb0) + fB[nf].x, 0.f);
                    o.y = fmaxf(fmaf(C[mf][nf][3], s1, bb1) + fB[nf].y, 0.f);
                    *(float2*)(out + (size_t)rowB * 256 + col) = o;
                }
            }
        }
        __syncthreads();
        cnt++;
    }
}

// ---------------------------------------------------------------------------
extern "C" void kernel_launch(void* const* d_in, const int* in_sizes, int n_in,
                              void* d_out, int out_size)
{
    const float* feat = (const float*)d_in[0];
    const int*   nbr  = (const int*)  d_in[1];
    const float* w1   = (const float*)d_in[2];
    const float* s1   = (const float*)d_in[3];
    const float* b1   = (const float*)d_in[4];
    const float* w2   = (const float*)d_in[5];
    const float* s2   = (const float*)d_in[6];
    const float* b2   = (const float*)d_in[7];
    const float* w3   = (const float*)d_in[8];
    const float* s3   = (const float*)d_in[9];
    const float* b3   = (const float*)d_in[10];
    float* out = (float*)d_out;

    int N = in_sizes[0] / 256;
    if (N > MAX_N) N = MAX_N;
    int tiles128 = (N + 127) >> 7;
    int tiles64  = (N + 63) >> 6;

    const int sm1 = 98304;
    const int sm2 = 212992;
    const int sm3 = 98304;

    cudaFuncSetAttribute(conv1_k, cudaFuncAttributeMaxDynamicSharedMemorySize, sm1);
    cudaFuncSetAttribute(conv2_k, cudaFuncAttributeMaxDynamicSharedMemorySize, sm2);
    cudaFuncSetAttribute(conv3_k, cudaFuncAttributeMaxDynamicSharedMemorySize, sm3);

    prep_weights<<<64, 256>>>(w1, w2, w3);
    conv1_k<<<296, 256, sm1>>>(feat, s1, b1, N, tiles64);
    conv2_k<<<148, 512, sm2>>>(nbr, s2, b2, N, tiles128);
    conv3_k<<<296, 256, sm3>>>(feat, s3, b3, out, N, tiles128);
}

// round 8
// speedup vs baseline: 1.5320x; 1.5320x over previous
#include <cuda_runtime.h>
#include <cuda_fp16.h>
#include <cstdint>

#define MAX_N 100000

// Single-plane fp16 intermediates; hi/lo fp16 split weights (transposed [n][k])
__device__ __align__(16) __half g_mid1[MAX_N * 64];
__device__ __align__(16) __half g_mid2[MAX_N * 64];
__device__ __align__(16) __half g_w1h[64 * 256], g_w1l[64 * 256];
__device__ __align__(16) __half g_w2h[9 * 64 * 64], g_w2l[9 * 64 * 64];
__device__ __align__(16) __half g_w3h[256 * 64], g_w3l[256 * 64];

// ---------------- helpers ----------------
__device__ __forceinline__ uint32_t smem_u32(const void* p) {
    uint32_t a;
    asm("{ .reg .u64 t; cvta.to.shared.u64 t, %1; cvt.u32.u64 %0, t; }" : "=r"(a) : "l"(p));
    return a;
}
__device__ __forceinline__ uint32_t pack2h(float a, float b) {
    __half2 h = __floats2half2_rn(a, b);
    return *(uint32_t*)&h;
}
__device__ __forceinline__ void cpa16(uint32_t dst, const void* src, int srcsize) {
    asm volatile("cp.async.cg.shared.global [%0], [%1], 16, %2;"
                 :: "r"(dst), "l"(src), "r"(srcsize));
}
#define CP_COMMIT() asm volatile("cp.async.commit_group;" ::: "memory")
#define CP_WAIT1()  asm volatile("cp.async.wait_group 1;" ::: "memory")
#define CP_WAIT0()  asm volatile("cp.async.wait_group 0;" ::: "memory")

__device__ __forceinline__ void mma_f16(float* c, const uint32_t* a, uint32_t b0, uint32_t b1) {
    asm volatile(
        "mma.sync.aligned.m16n8k16.row.col.f32.f16.f16.f32 "
        "{%0,%1,%2,%3}, {%4,%5,%6,%7}, {%8,%9}, {%0,%1,%2,%3};"
        : "+f"(c[0]), "+f"(c[1]), "+f"(c[2]), "+f"(c[3])
        : "r"(a[0]), "r"(a[1]), "r"(a[2]), "r"(a[3]), "r"(b0), "r"(b1));
}
__device__ __forceinline__ void ldsm4(uint32_t* r, uint32_t a) {
    asm volatile("ldmatrix.sync.aligned.m8n8.x4.shared.b16 {%0,%1,%2,%3}, [%4];"
                 : "=r"(r[0]), "=r"(r[1]), "=r"(r[2]), "=r"(r[3]) : "r"(a));
}

struct AF { uint32_t h[4]; };
struct BF2 { uint32_t h[4], l[4]; };

// A plane: [rows][64 fp16] stride 128B, chunk swizzle c^=row&7. kc0 in {0,2,4,6}.
__device__ __forceinline__ AF load_af(uint32_t aU, int lane, int m0, int kc0) {
    int row = m0 + (lane & 15);
    int kc = kc0 + (lane >> 4);
    uint32_t off = row * 128 + (((kc ^ row) & 7)) * 16;
    AF f; ldsm4(f.h, aU + off);
    return f;
}
// B planes: [n rows][K fp16] stride bytes; frags for n0 and n0+8 at {kc0,kc0+1}
__device__ __forceinline__ BF2 load_bf2(uint32_t hU, uint32_t lU, int stride, int lane,
                                        int n0, int kc0) {
    int row = n0 + (lane & 7) + ((lane >> 4) << 3);
    int kc = kc0 + ((lane >> 3) & 1);
    uint32_t off = row * stride + ((kc & ~7) | ((kc ^ row) & 7)) * 16;
    BF2 f; ldsm4(f.h, hU + off); ldsm4(f.l, lU + off);
    return f;
}
// 2-pass: A*(B_hi) + A*(B_lo)
__device__ __forceinline__ void mma2v(float* c, const AF& a, uint32_t bh0, uint32_t bh1,
                                      uint32_t bl0, uint32_t bl1) {
    mma_f16(c, a.h, bh0, bh1);
    mma_f16(c, a.h, bl0, bl1);
}

// ---------------- prep: split weights to fp16 hi/lo, transpose to [n][k] ----
__global__ void prep_weights(const float* __restrict__ w1, const float* __restrict__ w2,
                             const float* __restrict__ w3) {
    int tid = blockIdx.x * blockDim.x + threadIdx.x;
    int nt = gridDim.x * blockDim.x;
    for (int i = tid; i < 64 * 256; i += nt) {
        int n = i >> 8, k = i & 255;
        float x = w1[k * 64 + n];
        __half h = __float2half_rn(x);
        g_w1h[i] = h; g_w1l[i] = __float2half_rn(x - __half2float(h));
    }
    for (int i = tid; i < 9 * 64 * 64; i += nt) {
        int ko = i >> 12, n = (i >> 6) & 63, k = i & 63;
        float x = w2[ko * 4096 + k * 64 + n];
        __half h = __float2half_rn(x);
        g_w2h[i] = h; g_w2l[i] = __float2half_rn(x - __half2float(h));
    }
    for (int i = tid; i < 256 * 64; i += nt) {
        int n = i >> 6, k = i & 63;
        float x = w3[k * 256 + n];
        __half h = __float2half_rn(x);
        g_w3h[i] = h; g_w3l[i] = __float2half_rn(x - __half2float(h));
    }
}

// ===========================================================================
// conv1: M64 tiles, K=256 (4 panels of 64), 256 thr, 2 CTAs/SM.
// smem: Bh 32KB @0 | Bl 32KB @32768 | A 2buf x 8KB @65536 = 80KB
// ===========================================================================
__global__ void __launch_bounds__(256, 2) conv1_k(
    const float* __restrict__ feat, const float* __restrict__ scale,
    const float* __restrict__ bias, int N, int tiles)
{
    extern __shared__ char smem[];
    const uint32_t smU = smem_u32(smem);
    const int tid = threadIdx.x, w = tid >> 5, lane = tid & 31;
    const int g = lane >> 2, tg = lane & 3;
    const int m0w = (w & 1) * 32, n0w = (w >> 1) * 16;
    const int sr = tid >> 2, sq = tid & 3;   // 64 rows x 4 chunks(16 floats)

    // stage B planes [64][256 fp16] with swizzle (stride 512B)
    for (int e = tid; e < 2048; e += 256) {
        int n = e >> 5, kc = e & 31;
        int off = n * 512 + ((kc & ~7) | ((kc ^ n) & 7)) * 16;
        *(uint4*)(smem + off)         = *(const uint4*)(g_w1h + n * 256 + kc * 8);
        *(uint4*)(smem + 32768 + off) = *(const uint4*)(g_w1l + n * 256 + kc * 8);
    }

    float4 nx[4];
    {
        int grow = (blockIdx.x << 6) + sr;
        if (grow < N) {
            const float4* s = (const float4*)(feat + (size_t)grow * 256 + sq * 16);
            nx[0] = s[0]; nx[1] = s[1]; nx[2] = s[2]; nx[3] = s[3];
        } else nx[0] = nx[1] = nx[2] = nx[3] = make_float4(0.f, 0.f, 0.f, 0.f);
    }
    __syncthreads();

    for (int t = blockIdx.x; t < tiles; t += gridDim.x) {
        const int row0 = t << 6;
        float C[2][2][4] = {};
        #pragma unroll
        for (int p = 0; p < 4; p++) {
            char* A = smem + 65536 + (p & 1) * 8192;
            #pragma unroll
            for (int j = 0; j < 2; j++) {
                float4 u = nx[2 * j], v = nx[2 * j + 1];
                uint4 H;
                H.x = pack2h(u.x, u.y); H.y = pack2h(u.z, u.w);
                H.z = pack2h(v.x, v.y); H.w = pack2h(v.z, v.w);
                int c = sq * 2 + j;
                int off = sr * 128 + ((c ^ sr) & 7) * 16;
                *(uint4*)(A + off) = H;
            }
            __syncthreads();
            {
                int tn = (p < 3) ? t : t + gridDim.x;
                int pn = (p < 3) ? p + 1 : 0;
                int grow = (tn << 6) + sr;
                if (grow < N) {
                    const float4* s = (const float4*)(feat + (size_t)grow * 256 + pn * 64 + sq * 16);
                    nx[0] = s[0]; nx[1] = s[1]; nx[2] = s[2]; nx[3] = s[3];
                } else nx[0] = nx[1] = nx[2] = nx[3] = make_float4(0.f, 0.f, 0.f, 0.f);
            }
            const uint32_t AU = smU + 65536 + (p & 1) * 8192;
            #pragma unroll
            for (int s = 0; s < 4; s++) {
                AF a0 = load_af(AU, lane, m0w, s * 2);
                AF a1 = load_af(AU, lane, m0w + 16, s * 2);
                BF2 b = load_bf2(smU, smU + 32768, 512, lane, n0w, p * 8 + s * 2);
                mma2v(C[0][0], a0, b.h[0], b.h[1], b.l[0], b.l[1]);
                mma2v(C[0][1], a0, b.h[2], b.h[3], b.l[2], b.l[3]);
                mma2v(C[1][0], a1, b.h[0], b.h[1], b.l[0], b.l[1]);
                mma2v(C[1][1], a1, b.h[2], b.h[3], b.l[2], b.l[3]);
            }
        }
        #pragma unroll
        for (int mf = 0; mf < 2; mf++)
        #pragma unroll
        for (int nf = 0; nf < 2; nf++) {
            int row = row0 + m0w + mf * 16 + g;
            int col = n0w + nf * 8 + 2 * tg;
            float s0 = __ldg(scale + col), s1 = __ldg(scale + col + 1);
            float bb0 = __ldg(bias + col), bb1 = __ldg(bias + col + 1);
            if (row < N) {
                *(uint32_t*)(g_mid1 + (size_t)row * 64 + col) =
                    pack2h(fmaxf(fmaf(C[mf][nf][0], s0, bb0), 0.f),
                           fmaxf(fmaf(C[mf][nf][1], s1, bb1), 0.f));
            }
            if (row + 8 < N) {
                *(uint32_t*)(g_mid1 + (size_t)(row + 8) * 64 + col) =
                    pack2h(fmaxf(fmaf(C[mf][nf][2], s0, bb0), 0.f),
                           fmaxf(fmaf(C[mf][nf][3], s1, bb1), 0.f));
            }
        }
    }
}

// ===========================================================================
// conv2: 9x gathered [128,64]@[64,64], double-buffered single-plane gather.
// smem: B 9 x (h 8KB + l 8KB) = 144KB @0 | A 2 x 16KB @147456 -> 176KB total
// ===========================================================================
__global__ void __launch_bounds__(512) conv2_k(
    const int* __restrict__ nbr, const float* __restrict__ scale,
    const float* __restrict__ bias, int N, int tiles)
{
    extern __shared__ char smem[];
    const uint32_t smU = smem_u32(smem);
    const uint32_t AU = smU + 147456;
    const int tid = threadIdx.x, w = tid >> 5, lane = tid & 31;
    const int g = lane >> 2, tg = lane & 3;
    const int m0w = (w & 3) * 32, n0w = (w >> 2) * 16;
    const int sr = tid >> 2, sq = tid & 3;

    for (int e = tid; e < 4608; e += 512) {
        int ko = e >> 9, r = e & 511, n = r >> 3, kc = r & 7;
        int off = n * 128 + ((kc ^ n) & 7) * 16;
        *(uint4*)(smem + ko * 16384 + off)        = *(const uint4*)(g_w2h + ko * 4096 + n * 64 + kc * 8);
        *(uint4*)(smem + ko * 16384 + 8192 + off) = *(const uint4*)(g_w2l + ko * 4096 + n * 64 + kc * 8);
    }
    __syncthreads();

    const int c0 = sq * 2, c1 = sq * 2 + 1;
    const uint32_t offA0 = sr * 128 + ((c0 ^ sr) & 7) * 16;
    const uint32_t offA1 = sr * 128 + ((c1 ^ sr) & 7) * 16;

    for (int t = blockIdx.x; t < tiles; t += gridDim.x) {
        const int row0 = t << 7;
        const int grow = row0 + sr;
        int nidx9[9];
        #pragma unroll
        for (int ko = 0; ko < 9; ko++)
            nidx9[ko] = (grow < N) ? __ldg(nbr + (size_t)grow * 9 + ko) : N;

        {   // prologue gather ko=0 -> buf0 (zero-fill on sentinel)
            int nn = nidx9[0];
            int sz = (nn < N) ? 16 : 0;
            const __half* src = g_mid1 + (size_t)(nn < N ? nn : 0) * 64;
            cpa16(AU + offA0, src + c0 * 8, sz);
            cpa16(AU + offA1, src + c1 * 8, sz);
            CP_COMMIT();
        }

        float C[2][2][4] = {};
        #pragma unroll
        for (int ko = 0; ko < 9; ko++) {
            CP_WAIT0();
            __syncthreads();
            if (ko < 8) {
                int nn = nidx9[ko + 1];
                int sz = (nn < N) ? 16 : 0;
                const __half* src = g_mid1 + (size_t)(nn < N ? nn : 0) * 64;
                uint32_t Ab = AU + ((ko + 1) & 1) * 16384;
                cpa16(Ab + offA0, src + c0 * 8, sz);
                cpa16(Ab + offA1, src + c1 * 8, sz);
                CP_COMMIT();
            }
            const uint32_t AbU = AU + (ko & 1) * 16384;
            const uint32_t BhU = smU + ko * 16384, BlU = BhU + 8192;
            #pragma unroll
            for (int s = 0; s < 4; s++) {
                AF a0 = load_af(AbU, lane, m0w, s * 2);
                AF a1 = load_af(AbU, lane, m0w + 16, s * 2);
                BF2 b = load_bf2(BhU, BlU, 128, lane, n0w, s * 2);
                mma2v(C[0][0], a0, b.h[0], b.h[1], b.l[0], b.l[1]);
                mma2v(C[0][1], a0, b.h[2], b.h[3], b.l[2], b.l[3]);
                mma2v(C[1][0], a1, b.h[0], b.h[1], b.l[0], b.l[1]);
                mma2v(C[1][1], a1, b.h[2], b.h[3], b.l[2], b.l[3]);
            }
        }
        #pragma unroll
        for (int mf = 0; mf < 2; mf++)
        #pragma unroll
        for (int nf = 0; nf < 2; nf++) {
            int row = row0 + m0w + mf * 16 + g;
            int col = n0w + nf * 8 + 2 * tg;
            float s0 = __ldg(scale + col), s1 = __ldg(scale + col + 1);
            float bb0 = __ldg(bias + col), bb1 = __ldg(bias + col + 1);
            if (row < N) {
                *(uint32_t*)(g_mid2 + (size_t)row * 64 + col) =
                    pack2h(fmaxf(fmaf(C[mf][nf][0], s0, bb0), 0.f),
                           fmaxf(fmaf(C[mf][nf][1], s1, bb1), 0.f));
            }
            if (row + 8 < N) {
                *(uint32_t*)(g_mid2 + (size_t)(row + 8) * 64 + col) =
                    pack2h(fmaxf(fmaf(C[mf][nf][2], s0, bb0), 0.f),
                           fmaxf(fmaf(C[mf][nf][3], s1, bb1), 0.f));
            }
        }
        __syncthreads();
    }
}

// ===========================================================================
// conv3: M128 K64, two N128 halves; 256 thr, 2 CTAs/SM.
// smem: Bh 16KB @0 | Bl @16384 | A 2buf x 16KB @32768 = 64KB
// ===========================================================================
__global__ void __launch_bounds__(256, 2) conv3_k(
    const float* __restrict__ feat, const float* __restrict__ scale,
    const float* __restrict__ bias, float* __restrict__ out, int N, int tiles)
{
    extern __shared__ char smem[];
    const uint32_t smU = smem_u32(smem);
    const uint32_t AU = smU + 32768;
    const int tid = threadIdx.x, w = tid >> 5, lane = tid & 31;
    const int g = lane >> 2, tg = lane & 3;
    const int nhalf = blockIdx.x & 1;
    const int t0 = blockIdx.x >> 1, tstep = gridDim.x >> 1;
    const int m0w = (w & 3) * 32, n0l = (w >> 2) * 64;
    const int colbase = nhalf * 128;
    const int sr = tid >> 1, sq = tid & 1;   // 128 rows x 2 half-rows

    for (int e = tid; e < 1024; e += 256) {
        int n = e >> 3, kc = e & 7;
        int off = n * 128 + ((kc ^ n) & 7) * 16;
        *(uint4*)(smem + off)         = *(const uint4*)(g_w3h + (colbase + n) * 64 + kc * 8);
        *(uint4*)(smem + 16384 + off) = *(const uint4*)(g_w3l + (colbase + n) * 64 + kc * 8);
    }

    {   // prologue: prefetch tile t0 -> buf0
        int grow = (t0 << 7) + sr;
        int sz = (grow < N) ? 16 : 0;
        const __half* src = g_mid2 + (size_t)(grow < N ? grow : 0) * 64;
        #pragma unroll
        for (int j = 0; j < 4; j++) {
            int c = sq * 4 + j;
            uint32_t off = sr * 128 + ((c ^ sr) & 7) * 16;
            cpa16(AU + off, src + c * 8, sz);
        }
        CP_COMMIT();
    }

    int cnt = 0;
    for (int t = t0; t < tiles; t += tstep) {
        const int row0 = t << 7;
        const int b = cnt & 1;
        {   // prefetch next tile into other buffer
            int grow = ((t + tstep) << 7) + sr;
            int sz = (grow < N) ? 16 : 0;
            const __half* src = g_mid2 + (size_t)(grow < N ? grow : 0) * 64;
            uint32_t Ab = AU + (b ^ 1) * 16384;
            #pragma unroll
            for (int j = 0; j < 4; j++) {
                int c = sq * 4 + j;
                uint32_t off = sr * 128 + ((c ^ sr) & 7) * 16;
                cpa16(Ab + off, src + c * 8, sz);
            }
            CP_COMMIT();
        }
        CP_WAIT1();
        __syncthreads();

        const uint32_t AbU = AU + b * 16384;
        float C[2][8][4] = {};
        #pragma unroll
        for (int s = 0; s < 4; s++) {
            AF a0 = load_af(AbU, lane, m0w, s * 2);
            AF a1 = load_af(AbU, lane, m0w + 16, s * 2);
            #pragma unroll
            for (int nb = 0; nb < 4; nb++) {
                BF2 bb = load_bf2(smU, smU + 16384, 128, lane, n0l + nb * 16, s * 2);
                mma2v(C[0][2 * nb],     a0, bb.h[0], bb.h[1], bb.l[0], bb.l[1]);
                mma2v(C[0][2 * nb + 1], a0, bb.h[2], bb.h[3], bb.l[2], bb.l[3]);
                mma2v(C[1][2 * nb],     a1, bb.h[0], bb.h[1], bb.l[0], bb.l[1]);
                mma2v(C[1][2 * nb + 1], a1, bb.h[2], bb.h[3], bb.l[2], bb.l[3]);
            }
        }
        #pragma unroll
        for (int mf = 0; mf < 2; mf++)
        #pragma unroll
        for (int nf = 0; nf < 8; nf++) {
            int row = row0 + m0w + mf * 16 + g;
            int col = colbase + n0l + nf * 8 + 2 * tg;
            float s0 = __ldg(scale + col), s1 = __ldg(scale + col + 1);
            float bb0 = __ldg(bias + col), bb1 = __ldg(bias + col + 1);
            if (row < N) {
                float2 f = *(const float2*)(feat + (size_t)row * 256 + col);
                float2 o;
                o.x = fmaxf(fmaf(C[mf][nf][0], s0, bb0) + f.x, 0.f);
                o.y = fmaxf(fmaf(C[mf][nf][1], s1, bb1) + f.y, 0.f);
                *(float2*)(out + (size_t)row * 256 + col) = o;
            }
            if (row + 8 < N) {
                float2 f = *(const float2*)(feat + (size_t)(row + 8) * 256 + col);
                float2 o;
                o.x = fmaxf(fmaf(C[mf][nf][2], s0, bb0) + f.x, 0.f);
                o.y = fmaxf(fmaf(C[mf][nf][3], s1, bb1) + f.y, 0.f);
                *(float2*)(out + (size_t)(row + 8) * 256 + col) = o;
            }
        }
        __syncthreads();
        cnt++;
    }
}

// ---------------------------------------------------------------------------
extern "C" void kernel_launch(void* const* d_in, const int* in_sizes, int n_in,
                              void* d_out, int out_size)
{
    const float* feat = (const float*)d_in[0];
    const int*   nbr  = (const int*)  d_in[1];
    const float* w1   = (const float*)d_in[2];
    const float* s1   = (const float*)d_in[3];
    const float* b1   = (const float*)d_in[4];
    const float* w2   = (const float*)d_in[5];
    const float* s2   = (const float*)d_in[6];
    const float* b2   = (const float*)d_in[7];
    const float* w3   = (const float*)d_in[8];
    const float* s3   = (const float*)d_in[9];
    const float* b3   = (const float*)d_in[10];
    float* out = (float*)d_out;

    int N = in_sizes[0] / 256;
    if (N > MAX_N) N = MAX_N;
    int tiles128 = (N + 127) >> 7;
    int tiles64  = (N + 63) >> 6;

    const int sm1 = 81920;    // 80KB -> 2 CTAs/SM
    const int sm2 = 180224;   // 176KB -> 1 CTA/SM
    const int sm3 = 65536;    // 64KB -> 2 CTAs/SM

    cudaFuncSetAttribute(conv1_k, cudaFuncAttributeMaxDynamicSharedMemorySize, sm1);
    cudaFuncSetAttribute(conv2_k, cudaFuncAttributeMaxDynamicSharedMemorySize, sm2);
    cudaFuncSetAttribute(conv3_k, cudaFuncAttributeMaxDynamicSharedMemorySize, sm3);

    prep_weights<<<64, 256>>>(w1, w2, w3);
    conv1_k<<<296, 256, sm1>>>(feat, s1, b1, N, tiles64);
    conv2_k<<<148, 512, sm2>>>(nbr, s2, b2, N, tiles128);
    conv3_k<<<296, 256, sm3>>>(feat, s3, b3, out, N, tiles128);
}

// round 9
// speedup vs baseline: 1.7201x; 1.1228x over previous
#include <cuda_runtime.h>
#include <cuda_fp16.h>
#include <cstdint>

#define MAX_N 100000

// Single-plane fp16 intermediates and weights (transposed [n][k])
__device__ __align__(16) __half g_mid1[MAX_N * 64];
__device__ __align__(16) __half g_mid2[MAX_N * 64];
__device__ __align__(16) __half g_w1[64 * 256];
__device__ __align__(16) __half g_w2[9 * 64 * 64];
__device__ __align__(16) __half g_w3[256 * 64];

// ---------------- helpers ----------------
__device__ __forceinline__ uint32_t smem_u32(const void* p) {
    uint32_t a;
    asm("{ .reg .u64 t; cvta.to.shared.u64 t, %1; cvt.u32.u64 %0, t; }" : "=r"(a) : "l"(p));
    return a;
}
__device__ __forceinline__ uint32_t pack2h(float a, float b) {
    __half2 h = __floats2half2_rn(a, b);
    return *(uint32_t*)&h;
}
__device__ __forceinline__ void cpa16(uint32_t dst, const void* src, int srcsize) {
    asm volatile("cp.async.cg.shared.global [%0], [%1], 16, %2;"
                 :: "r"(dst), "l"(src), "r"(srcsize));
}
#define CP_COMMIT() asm volatile("cp.async.commit_group;" ::: "memory")
#define CP_WAIT1()  asm volatile("cp.async.wait_group 1;" ::: "memory")
#define CP_WAIT0()  asm volatile("cp.async.wait_group 0;" ::: "memory")

__device__ __forceinline__ void mma_f16(float* c, const uint32_t* a, uint32_t b0, uint32_t b1) {
    asm volatile(
        "mma.sync.aligned.m16n8k16.row.col.f32.f16.f16.f32 "
        "{%0,%1,%2,%3}, {%4,%5,%6,%7}, {%8,%9}, {%0,%1,%2,%3};"
        : "+f"(c[0]), "+f"(c[1]), "+f"(c[2]), "+f"(c[3])
        : "r"(a[0]), "r"(a[1]), "r"(a[2]), "r"(a[3]), "r"(b0), "r"(b1));
}
__device__ __forceinline__ void ldsm4(uint32_t* r, uint32_t a) {
    asm volatile("ldmatrix.sync.aligned.m8n8.x4.shared.b16 {%0,%1,%2,%3}, [%4];"
                 : "=r"(r[0]), "=r"(r[1]), "=r"(r[2]), "=r"(r[3]) : "r"(a));
}

struct AF { uint32_t h[4]; };
struct BF { uint32_t h[4]; };

// A plane: [rows][64 fp16] stride 128B, chunk swizzle c^=row&7. kc0 in {0,2,4,6}.
__device__ __forceinline__ AF load_af(uint32_t aU, int lane, int m0, int kc0) {
    int row = m0 + (lane & 15);
    int kc = kc0 + (lane >> 4);
    uint32_t off = row * 128 + (((kc ^ row) & 7)) * 16;
    AF f; ldsm4(f.h, aU + off);
    return f;
}
// B plane: [n rows][K fp16] stride bytes; frags for n0 and n0+8 at {kc0,kc0+1}
__device__ __forceinline__ BF load_bf(uint32_t bU, int stride, int lane, int n0, int kc0) {
    int row = n0 + (lane & 7) + ((lane >> 4) << 3);
    int kc = kc0 + ((lane >> 3) & 1);
    uint32_t off = row * stride + ((kc & ~7) | ((kc ^ row) & 7)) * 16;
    BF f; ldsm4(f.h, bU + off);
    return f;
}

// ---------------- prep: round weights to fp16, transpose to [n][k] --------
__global__ void prep_weights(const float* __restrict__ w1, const float* __restrict__ w2,
                             const float* __restrict__ w3) {
    int tid = blockIdx.x * blockDim.x + threadIdx.x;
    int nt = gridDim.x * blockDim.x;
    for (int i = tid; i < 64 * 256; i += nt) {
        int n = i >> 8, k = i & 255;
        g_w1[i] = __float2half_rn(w1[k * 64 + n]);
    }
    for (int i = tid; i < 9 * 64 * 64; i += nt) {
        int ko = i >> 12, n = (i >> 6) & 63, k = i & 63;
        g_w2[i] = __float2half_rn(w2[ko * 4096 + k * 64 + n]);
    }
    for (int i = tid; i < 256 * 64; i += nt) {
        int n = i >> 6, k = i & 63;
        g_w3[i] = __float2half_rn(w3[k * 256 + n]);
    }
}

// ===========================================================================
// conv1: M64 tiles, K=256 (4 panels of 64), 256 thr, 2 CTAs/SM.
// smem: B 32KB @0 | A 2buf x 8KB @32768 = 48KB
// ===========================================================================
__global__ void __launch_bounds__(256, 2) conv1_k(
    const float* __restrict__ feat, const float* __restrict__ scale,
    const float* __restrict__ bias, int N, int tiles)
{
    extern __shared__ char smem[];
    const uint32_t smU = smem_u32(smem);
    const int tid = threadIdx.x, w = tid >> 5, lane = tid & 31;
    const int g = lane >> 2, tg = lane & 3;
    const int m0w = (w & 1) * 32, n0w = (w >> 1) * 16;
    const int sr = tid >> 2, sq = tid & 3;   // 64 rows x 4 chunks(16 floats)

    // stage B plane [64][256 fp16] with swizzle (stride 512B)
    for (int e = tid; e < 2048; e += 256) {
        int n = e >> 5, kc = e & 31;
        int off = n * 512 + ((kc & ~7) | ((kc ^ n) & 7)) * 16;
        *(uint4*)(smem + off) = *(const uint4*)(g_w1 + n * 256 + kc * 8);
    }

    float4 nx[4];
    {
        int grow = (blockIdx.x << 6) + sr;
        if (grow < N) {
            const float4* s = (const float4*)(feat + (size_t)grow * 256 + sq * 16);
            nx[0] = s[0]; nx[1] = s[1]; nx[2] = s[2]; nx[3] = s[3];
        } else nx[0] = nx[1] = nx[2] = nx[3] = make_float4(0.f, 0.f, 0.f, 0.f);
    }
    __syncthreads();

    for (int t = blockIdx.x; t < tiles; t += gridDim.x) {
        const int row0 = t << 6;
        float C[2][2][4] = {};
        #pragma unroll
        for (int p = 0; p < 4; p++) {
            char* A = smem + 32768 + (p & 1) * 8192;
            #pragma unroll
            for (int j = 0; j < 2; j++) {
                float4 u = nx[2 * j], v = nx[2 * j + 1];
                uint4 H;
                H.x = pack2h(u.x, u.y); H.y = pack2h(u.z, u.w);
                H.z = pack2h(v.x, v.y); H.w = pack2h(v.z, v.w);
                int c = sq * 2 + j;
                int off = sr * 128 + ((c ^ sr) & 7) * 16;
                *(uint4*)(A + off) = H;
            }
            __syncthreads();
            {
                int tn = (p < 3) ? t : t + gridDim.x;
                int pn = (p < 3) ? p + 1 : 0;
                int grow = (tn << 6) + sr;
                if (grow < N) {
                    const float4* s = (const float4*)(feat + (size_t)grow * 256 + pn * 64 + sq * 16);
                    nx[0] = s[0]; nx[1] = s[1]; nx[2] = s[2]; nx[3] = s[3];
                } else nx[0] = nx[1] = nx[2] = nx[3] = make_float4(0.f, 0.f, 0.f, 0.f);
            }
            const uint32_t AU = smU + 32768 + (p & 1) * 8192;
            #pragma unroll
            for (int s = 0; s < 4; s++) {
                AF a0 = load_af(AU, lane, m0w, s * 2);
                AF a1 = load_af(AU, lane, m0w + 16, s * 2);
                BF b = load_bf(smU, 512, lane, n0w, p * 8 + s * 2);
                mma_f16(C[0][0], a0.h, b.h[0], b.h[1]);
                mma_f16(C[0][1], a0.h, b.h[2], b.h[3]);
                mma_f16(C[1][0], a1.h, b.h[0], b.h[1]);
                mma_f16(C[1][1], a1.h, b.h[2], b.h[3]);
            }
        }
        #pragma unroll
        for (int mf = 0; mf < 2; mf++)
        #pragma unroll
        for (int nf = 0; nf < 2; nf++) {
            int row = row0 + m0w + mf * 16 + g;
            int col = n0w + nf * 8 + 2 * tg;
            float s0 = __ldg(scale + col), s1 = __ldg(scale + col + 1);
            float bb0 = __ldg(bias + col), bb1 = __ldg(bias + col + 1);
            if (row < N) {
                *(uint32_t*)(g_mid1 + (size_t)row * 64 + col) =
                    pack2h(fmaxf(fmaf(C[mf][nf][0], s0, bb0), 0.f),
                           fmaxf(fmaf(C[mf][nf][1], s1, bb1), 0.f));
            }
            if (row + 8 < N) {
                *(uint32_t*)(g_mid1 + (size_t)(row + 8) * 64 + col) =
                    pack2h(fmaxf(fmaf(C[mf][nf][2], s0, bb0), 0.f),
                           fmaxf(fmaf(C[mf][nf][3], s1, bb1), 0.f));
            }
        }
    }
}

// ===========================================================================
// conv2: 9x gathered [128,64]@[64,64], double-buffered single-plane gather.
// smem: B 9 x 8KB = 72KB @0 | A 2 x 16KB @73728 -> 104KB total, 512 thr.
// ===========================================================================
__global__ void __launch_bounds__(512) conv2_k(
    const int* __restrict__ nbr, const float* __restrict__ scale,
    const float* __restrict__ bias, int N, int tiles)
{
    extern __shared__ char smem[];
    const uint32_t smU = smem_u32(smem);
    const uint32_t AU = smU + 73728;
    const int tid = threadIdx.x, w = tid >> 5, lane = tid & 31;
    const int g = lane >> 2, tg = lane & 3;
    const int m0w = (w & 3) * 32, n0w = (w >> 2) * 16;
    const int sr = tid >> 2, sq = tid & 3;

    for (int e = tid; e < 4608; e += 512) {
        int ko = e >> 9, r = e & 511, n = r >> 3, kc = r & 7;
        int off = n * 128 + ((kc ^ n) & 7) * 16;
        *(uint4*)(smem + ko * 8192 + off) = *(const uint4*)(g_w2 + ko * 4096 + n * 64 + kc * 8);
    }
    __syncthreads();

    const int c0 = sq * 2, c1 = sq * 2 + 1;
    const uint32_t offA0 = sr * 128 + ((c0 ^ sr) & 7) * 16;
    const uint32_t offA1 = sr * 128 + ((c1 ^ sr) & 7) * 16;

    for (int t = blockIdx.x; t < tiles; t += gridDim.x) {
        const int row0 = t << 7;
        const int grow = row0 + sr;
        int nidx9[9];
        #pragma unroll
        for (int ko = 0; ko < 9; ko++)
            nidx9[ko] = (grow < N) ? __ldg(nbr + (size_t)grow * 9 + ko) : N;

        {   // prologue gather ko=0 -> buf0 (zero-fill on sentinel)
            int nn = nidx9[0];
            int sz = (nn < N) ? 16 : 0;
            const __half* src = g_mid1 + (size_t)(nn < N ? nn : 0) * 64;
            cpa16(AU + offA0, src + c0 * 8, sz);
            cpa16(AU + offA1, src + c1 * 8, sz);
            CP_COMMIT();
        }

        float C[2][2][4] = {};
        #pragma unroll
        for (int ko = 0; ko < 9; ko++) {
            CP_WAIT0();
            __syncthreads();
            if (ko < 8) {
                int nn = nidx9[ko + 1];
                int sz = (nn < N) ? 16 : 0;
                const __half* src = g_mid1 + (size_t)(nn < N ? nn : 0) * 64;
                uint32_t Ab = AU + ((ko + 1) & 1) * 16384;
                cpa16(Ab + offA0, src + c0 * 8, sz);
                cpa16(Ab + offA1, src + c1 * 8, sz);
                CP_COMMIT();
            }
            const uint32_t AbU = AU + (ko & 1) * 16384;
            const uint32_t BU = smU + ko * 8192;
            #pragma unroll
            for (int s = 0; s < 4; s++) {
                AF a0 = load_af(AbU, lane, m0w, s * 2);
                AF a1 = load_af(AbU, lane, m0w + 16, s * 2);
                BF b = load_bf(BU, 128, lane, n0w, s * 2);
                mma_f16(C[0][0], a0.h, b.h[0], b.h[1]);
                mma_f16(C[0][1], a0.h, b.h[2], b.h[3]);
                mma_f16(C[1][0], a1.h, b.h[0], b.h[1]);
                mma_f16(C[1][1], a1.h, b.h[2], b.h[3]);
            }
        }
        #pragma unroll
        for (int mf = 0; mf < 2; mf++)
        #pragma unroll
        for (int nf = 0; nf < 2; nf++) {
            int row = row0 + m0w + mf * 16 + g;
            int col = n0w + nf * 8 + 2 * tg;
            float s0 = __ldg(scale + col), s1 = __ldg(scale + col + 1);
            float bb0 = __ldg(bias + col), bb1 = __ldg(bias + col + 1);
            if (row < N) {
                *(uint32_t*)(g_mid2 + (size_t)row * 64 + col) =
                    pack2h(fmaxf(fmaf(C[mf][nf][0], s0, bb0), 0.f),
                           fmaxf(fmaf(C[mf][nf][1], s1, bb1), 0.f));
            }
            if (row + 8 < N) {
                *(uint32_t*)(g_mid2 + (size_t)(row + 8) * 64 + col) =
                    pack2h(fmaxf(fmaf(C[mf][nf][2], s0, bb0), 0.f),
                           fmaxf(fmaf(C[mf][nf][3], s1, bb1), 0.f));
            }
        }
        __syncthreads();
    }
}

// ===========================================================================
// conv3: M128 K64, two N128 halves; 256 thr, 2 CTAs/SM.
// smem: B 16KB @0 | A 2buf x 16KB @16384 = 48KB
// ===========================================================================
__global__ void __launch_bounds__(256, 2) conv3_k(
    const float* __restrict__ feat, const float* __restrict__ scale,
    const float* __restrict__ bias, float* __restrict__ out, int N, int tiles)
{
    extern __shared__ char smem[];
    const uint32_t smU = smem_u32(smem);
    const uint32_t AU = smU + 16384;
    const int tid = threadIdx.x, w = tid >> 5, lane = tid & 31;
    const int g = lane >> 2, tg = lane & 3;
    const int nhalf = blockIdx.x & 1;
    const int t0 = blockIdx.x >> 1, tstep = gridDim.x >> 1;
    const int m0w = (w & 3) * 32, n0l = (w >> 2) * 64;
    const int colbase = nhalf * 128;
    const int sr = tid >> 1, sq = tid & 1;   // 128 rows x 2 half-rows

    for (int e = tid; e < 1024; e += 256) {
        int n = e >> 3, kc = e & 7;
        int off = n * 128 + ((kc ^ n) & 7) * 16;
        *(uint4*)(smem + off) = *(const uint4*)(g_w3 + (colbase + n) * 64 + kc * 8);
    }

    {   // prologue: prefetch tile t0 -> buf0
        int grow = (t0 << 7) + sr;
        int sz = (grow < N) ? 16 : 0;
        const __half* src = g_mid2 + (size_t)(grow < N ? grow : 0) * 64;
        #pragma unroll
        for (int j = 0; j < 4; j++) {
            int c = sq * 4 + j;
            uint32_t off = sr * 128 + ((c ^ sr) & 7) * 16;
            cpa16(AU + off, src + c * 8, sz);
        }
        CP_COMMIT();
    }

    int cnt = 0;
    for (int t = t0; t < tiles; t += tstep) {
        const int row0 = t << 7;
        const int b = cnt & 1;
        {   // prefetch next tile into other buffer
            int grow = ((t + tstep) << 7) + sr;
            int sz = (grow < N) ? 16 : 0;
            const __half* src = g_mid2 + (size_t)(grow < N ? grow : 0) * 64;
            uint32_t Ab = AU + (b ^ 1) * 16384;
            #pragma unroll
            for (int j = 0; j < 4; j++) {
                int c = sq * 4 + j;
                uint32_t off = sr * 128 + ((c ^ sr) & 7) * 16;
                cpa16(Ab + off, src + c * 8, sz);
            }
            CP_COMMIT();
        }
        CP_WAIT1();
        __syncthreads();

        const uint32_t AbU = AU + b * 16384;
        float C[2][8][4] = {};
        #pragma unroll
        for (int s = 0; s < 4; s++) {
            AF a0 = load_af(AbU, lane, m0w, s * 2);
            AF a1 = load_af(AbU, lane, m0w + 16, s * 2);
            #pragma unroll
            for (int nb = 0; nb < 4; nb++) {
                BF bb = load_bf(smU, 128, lane, n0l + nb * 16, s * 2);
                mma_f16(C[0][2 * nb],     a0.h, bb.h[0], bb.h[1]);
                mma_f16(C[0][2 * nb + 1], a0.h, bb.h[2], bb.h[3]);
                mma_f16(C[1][2 * nb],     a1.h, bb.h[0], bb.h[1]);
                mma_f16(C[1][2 * nb + 1], a1.h, bb.h[2], bb.h[3]);
            }
        }
        #pragma unroll
        for (int mf = 0; mf < 2; mf++)
        #pragma unroll
        for (int nf = 0; nf < 8; nf++) {
            int row = row0 + m0w + mf * 16 + g;
            int col = colbase + n0l + nf * 8 + 2 * tg;
            float s0 = __ldg(scale + col), s1 = __ldg(scale + col + 1);
            float bb0 = __ldg(bias + col), bb1 = __ldg(bias + col + 1);
            if (row < N) {
                float2 f = *(const float2*)(feat + (size_t)row * 256 + col);
                float2 o;
                o.x = fmaxf(fmaf(C[mf][nf][0], s0, bb0) + f.x, 0.f);
                o.y = fmaxf(fmaf(C[mf][nf][1], s1, bb1) + f.y, 0.f);
                *(float2*)(out + (size_t)row * 256 + col) = o;
            }
            if (row + 8 < N) {
                float2 f = *(const float2*)(feat + (size_t)(row + 8) * 256 + col);
                float2 o;
                o.x = fmaxf(fmaf(C[mf][nf][2], s0, bb0) + f.x, 0.f);
                o.y = fmaxf(fmaf(C[mf][nf][3], s1, bb1) + f.y, 0.f);
                *(float2*)(out + (size_t)(row + 8) * 256 + col) = o;
            }
        }
        __syncthreads();
        cnt++;
    }
}

// ---------------------------------------------------------------------------
extern "C" void kernel_launch(void* const* d_in, const int* in_sizes, int n_in,
                              void* d_out, int out_size)
{
    const float* feat = (const float*)d_in[0];
    const int*   nbr  = (const int*)  d_in[1];
    const float* w1   = (const float*)d_in[2];
    const float* s1   = (const float*)d_in[3];
    const float* b1   = (const float*)d_in[4];
    const float* w2   = (const float*)d_in[5];
    const float* s2   = (const float*)d_in[6];
    const float* b2   = (const float*)d_in[7];
    const float* w3   = (const float*)d_in[8];
    const float* s3   = (const float*)d_in[9];
    const float* b3   = (const float*)d_in[10];
    float* out = (float*)d_out;

    int N = in_sizes[0] / 256;
    if (N > MAX_N) N = MAX_N;
    int tiles128 = (N + 127) >> 7;
    int tiles64  = (N + 63) >> 6;

    const int sm1 = 49152;    // 48KB -> 2 CTAs/SM
    const int sm2 = 106496;   // 104KB -> 1 CTA/SM
    const int sm3 = 49152;    // 48KB -> 2 CTAs/SM

    cudaFuncSetAttribute(conv1_k, cudaFuncAttributeMaxDynamicSharedMemorySize, sm1);
    cudaFuncSetAttribute(conv2_k, cudaFuncAttributeMaxDynamicSharedMemorySize, sm2);
    cudaFuncSetAttribute(conv3_k, cudaFuncAttributeMaxDynamicSharedMemorySize, sm3);

    prep_weights<<<64, 256>>>(w1, w2, w3);
    conv1_k<<<296, 256, sm1>>>(feat, s1, b1, N, tiles64);
    conv2_k<<<148, 512, sm2>>>(nbr, s2, b2, N, tiles128);
    conv3_k<<<296, 256, sm3>>>(feat, s3, b3, out, N, tiles128);
}